// round 15
// baseline (speedup 1.0000x reference)
#include <cuda_runtime.h>
#include <cuda_pipeline.h>
#include <cuda_fp16.h>
#include <math.h>
#include <stdint.h>

#define NN    40000
#define INITD 100
#define DD    200
#define FF    4
#define EE    800000
#define NRELD 800
#define BB    2048
#define HH2   100
#define NPAIR 6
#define FD    (FF*DD)   // 800

#define SUB_OFF 0
#define REL_OFF ((size_t)BB*FD)
#define X_OFF   ((size_t)2*BB*FD)
#define MI_OFF  ((size_t)2*BB*FD + (size_t)NN*FD)

typedef unsigned long long u64t;

// ---------------- scratch ----------------------------------------------------
__device__ float g_xA[(size_t)NN*FD];   // head-major fp32 (kw GEMM input)
__device__ float g_xB[(size_t)NN*FD];   // kw_raw temp
__device__ float g_kw[(size_t)NN*FD];
__device__ float g_th0[(size_t)NN*FD];  // layer0 tanh-part (fp32 head-major)
__device__ __align__(16) __half g_xhA[(size_t)NN*FD];  // fp16 x0 (layer0 gather)
__device__ __align__(16) __half g_xhB[(size_t)NN*FD];  // fp16 layer0 out (layer1 gather)
__device__ float g_r1[NRELD*DD];
__device__ float g_h[12*BB*HH2];
__device__ float g_o2[12*BB*DD];
__device__ int   g_deg[NN];
__device__ int   g_cur[NN];
__device__ int   g_rowptr[NN+1];
__device__ int   g_csrc[EE];
__device__ int   g_cet[EE];
__device__ int   g_bsums[256];
__device__ int   g_boffs[256];

// ---------------- packed f32x2 helpers ---------------------------------------
__device__ __forceinline__ void ffma2(u64t& d, u64t a, u64t b) {
    asm("fma.rn.f32x2 %0, %1, %2, %0;" : "+l"(d) : "l"(a), "l"(b));
}
__device__ __forceinline__ u64t dup2(float x) {
    u64t r; asm("mov.b64 %0, {%1, %2};" : "=l"(r) : "f"(x), "f"(x)); return r;
}
__device__ __forceinline__ float2 unpack2(u64t v) {
    float lo, hi; asm("mov.b64 {%0, %1}, %2;" : "=f"(lo), "=f"(hi) : "l"(v));
    return make_float2(lo, hi);
}

// ---------------- CSR build ---------------------------------------------------
__global__ void k_zero(float* mi) {
    int i = blockIdx.x*blockDim.x + threadIdx.x;
    if (i < NN) { g_deg[i] = 0; g_cur[i] = 0; }
    if (i == 0) *mi = 0.f;
}
__global__ void k_hist(const int* __restrict__ dst) {
    int e = blockIdx.x*blockDim.x + threadIdx.x;
    if (e < EE) atomicAdd(&g_deg[dst[e]], 1);
}
__global__ void k_scan1() {
    __shared__ int s[256];
    int tid = threadIdx.x;
    int i = blockIdx.x*256 + tid;
    int v = (i < NN) ? g_deg[i] : 0;
    s[tid] = v; __syncthreads();
    for (int off = 1; off < 256; off <<= 1) {
        int t = (tid >= off) ? s[tid-off] : 0;
        __syncthreads(); s[tid] += t; __syncthreads();
    }
    if (i < NN) g_rowptr[i] = s[tid] - v;
    if (tid == 255) g_bsums[blockIdx.x] = s[255];
}
__global__ void k_scan2(int nb) {
    __shared__ int s[256];
    int tid = threadIdx.x;
    int v = (tid < nb) ? g_bsums[tid] : 0;
    s[tid] = v; __syncthreads();
    for (int off = 1; off < 256; off <<= 1) {
        int t = (tid >= off) ? s[tid-off] : 0;
        __syncthreads(); s[tid] += t; __syncthreads();
    }
    if (tid < nb) g_boffs[tid] = s[tid] - v;
}
__global__ void k_scan3() {
    int tid = threadIdx.x;
    int i = blockIdx.x*256 + tid;
    if (i < NN) g_rowptr[i] += g_boffs[blockIdx.x];
    if (i == 0) g_rowptr[NN] = EE;
}
__global__ void k_fill(const int* __restrict__ src, const int* __restrict__ dst,
                       const int* __restrict__ et) {
    int e = blockIdx.x*blockDim.x + threadIdx.x;
    if (e >= EE) return;
    int d = dst[e];
    int pos = g_rowptr[d] + atomicAdd(&g_cur[d], 1);
    g_csrc[pos] = src[e];
    g_cet[pos]  = et[e];
}

// ---------------- SGEMM v5: 128x64, coalesced A, f32x2 ----------------------
__global__ __launch_bounds__(128, 4)
void k_sgemm4(const float* __restrict__ A, int lda,
              const float* __restrict__ B, int ldb,
              const float* __restrict__ bias,
              float* __restrict__ C, int ldc,
              __half* __restrict__ Ch,
              int M, int N, int K, int act, int hm) {
    __shared__ __align__(16) float As[2][16][128];
    __shared__ __align__(16) float Bs[2][16][64];
    int tid = threadIdx.x;
    int tx = tid & 7, ty = tid >> 3;
    int row0 = blockIdx.x*128, col0 = blockIdx.y*64;
    int bk = tid >> 3, bc = (tid & 7) * 8;
    int arow = tid >> 2;
    int ak4  = (tid & 3) * 4;

    u64t acc[4][8];
    #pragma unroll
    for (int i = 0; i < 4; i++)
        #pragma unroll
        for (int j = 0; j < 8; j++) acc[i][j] = 0ull;

    float pa[16], pb[8];
    int nkt = (K + 15) >> 4;
    #pragma unroll 1
    for (int kt = -1; kt < nkt; kt++) {
        bool fastA = false;
        if (kt + 1 < nkt) {
            int k0 = (kt + 1) * 16;
            fastA = (k0 + 16 <= K) && (row0 + 128 <= M);
            if (fastA) {
                #pragma unroll
                for (int it = 0; it < 4; it++) {
                    float4 v = *(const float4*)(A + (size_t)(row0 + arow + it*32)*lda + k0 + ak4);
                    pa[it*4+0] = v.x; pa[it*4+1] = v.y; pa[it*4+2] = v.z; pa[it*4+3] = v.w;
                }
            } else {
                int gr = row0 + tid;
                #pragma unroll
                for (int c = 0; c < 16; c++)
                    pa[c] = (gr < M && k0 + c < K) ? A[(size_t)gr*lda + k0 + c] : 0.f;
            }
            if (k0 + bk < K && col0 + 64 <= N) {
                const float* bp = B + (size_t)(k0 + bk)*ldb + col0 + bc;
                float4 v0=*(const float4*)bp, v1=*(const float4*)(bp+4);
                pb[0]=v0.x;pb[1]=v0.y;pb[2]=v0.z;pb[3]=v0.w;
                pb[4]=v1.x;pb[5]=v1.y;pb[6]=v1.z;pb[7]=v1.w;
            } else {
                #pragma unroll
                for (int c = 0; c < 8; c++) {
                    int gc = col0 + bc + c;
                    pb[c] = (k0 + bk < K && gc < N) ? B[(size_t)(k0+bk)*ldb + gc] : 0.f;
                }
            }
        }
        if (kt >= 0) {
            int cur = kt & 1;
            #pragma unroll
            for (int kk = 0; kk < 16; kk++) {
                const ulonglong2* ap2 = (const ulonglong2*)&As[cur][kk][ty*8];
                ulonglong2 aA = ap2[0];
                ulonglong2 aB = ap2[1];
                float4 bv0 = *(const float4*)&Bs[cur][kk][tx*8];
                float4 bv1 = *(const float4*)&Bs[cur][kk][tx*8+4];
                u64t b[8];
                b[0]=dup2(bv0.x); b[1]=dup2(bv0.y); b[2]=dup2(bv0.z); b[3]=dup2(bv0.w);
                b[4]=dup2(bv1.x); b[5]=dup2(bv1.y); b[6]=dup2(bv1.z); b[7]=dup2(bv1.w);
                #pragma unroll
                for (int j = 0; j < 8; j++) {
                    ffma2(acc[0][j], aA.x, b[j]);
                    ffma2(acc[1][j], aA.y, b[j]);
                    ffma2(acc[2][j], aB.x, b[j]);
                    ffma2(acc[3][j], aB.y, b[j]);
                }
            }
        }
        if (kt + 1 < nkt) {
            int nxt = (kt + 1) & 1;
            if (fastA) {
                #pragma unroll
                for (int it = 0; it < 4; it++) {
                    int rr = arow + it*32;
                    As[nxt][ak4+0][rr] = pa[it*4+0];
                    As[nxt][ak4+1][rr] = pa[it*4+1];
                    As[nxt][ak4+2][rr] = pa[it*4+2];
                    As[nxt][ak4+3][rr] = pa[it*4+3];
                }
            } else {
                #pragma unroll
                for (int c = 0; c < 16; c++) As[nxt][c][tid] = pa[c];
            }
            *(float4*)&Bs[nxt][bk][bc]   = make_float4(pb[0],pb[1],pb[2],pb[3]);
            *(float4*)&Bs[nxt][bk][bc+4] = make_float4(pb[4],pb[5],pb[6],pb[7]);
        }
        __syncthreads();
    }

    #pragma unroll
    for (int i = 0; i < 4; i++) {
        int r0 = row0 + ty*8 + i*2;
        #pragma unroll
        for (int j = 0; j < 8; j++) {
            int gc = col0 + tx*8 + j;
            if (gc >= N) continue;
            float2 p = unpack2(acc[i][j]);
            float bv = bias ? bias[gc] : 0.f;
            float v0 = p.x + bv, v1 = p.y + bv;
            if (act == 1) { v0 = tanhf(v0); v1 = tanhf(v1); }
            else if (act == 2) { v0 = (v0 > 0.f) ? v0 : 0.2f*v0; v1 = (v1 > 0.f) ? v1 : 0.2f*v1; }
            if (hm) {
                int f = gc / DD, d = gc - f*DD;
                size_t base = (size_t)f*NN*DD + d;
                if (r0 < M) {
                    C[base + (size_t)r0*DD] = v0;
                    if (Ch) Ch[base + (size_t)r0*DD] = __float2half(v0);
                }
                if (r0 + 1 < M) {
                    C[base + (size_t)(r0+1)*DD] = v1;
                    if (Ch) Ch[base + (size_t)(r0+1)*DD] = __float2half(v1);
                }
            } else {
                if (r0     < M) C[(size_t)r0    *ldc + gc] = v0;
                if (r0 + 1 < M) C[(size_t)(r0+1)*ldc + gc] = v1;
            }
        }
    }
}

// ---------------- kw softmax over F axis (head-major) ------------------------
__global__ void k_kwsm(const float* __restrict__ raw, float* __restrict__ kw) {
    int i = blockIdx.x*blockDim.x + threadIdx.x;
    if (i >= NN*DD) return;
    const float* p = raw + i;
    const size_t S = (size_t)NN*DD;
    float a0 = __ldcs(p), a1 = __ldcs(p+S), a2 = __ldcs(p+2*S), a3 = __ldcs(p+3*S);
    float m = fmaxf(fmaxf(a0, a1), fmaxf(a2, a3));
    float e0 = __expf(a0-m), e1 = __expf(a1-m), e2 = __expf(a2-m), e3 = __expf(a3-m);
    float inv = 1.f/(e0+e1+e2+e3);
    float* q = kw + i;
    __stcs(q, e0*inv); __stcs(q+S, e1*inv); __stcs(q+2*S, e2*inv); __stcs(q+3*S, e3*inv);
}

// ---------------- mulkw: xhB = half(th0 * kw)  (head-major elementwise) ------
__global__ void k_mulkw(const float* __restrict__ th0, const float* __restrict__ kw,
                        __half* __restrict__ xhB) {
    size_t i = (size_t)(blockIdx.x*blockDim.x + threadIdx.x) * 2;
    if (i >= (size_t)NN*FD) return;
    float2 t = *(const float2*)(th0 + i);
    float2 k = *(const float2*)(kw + i);
    __half2 h = __floats2half2_rn(t.x*k.x, t.y*k.y);
    *(__half2*)(xhB + i) = h;
}

// ---------------- attention layer: fp16 gathers, cp.async 3-slot ring --------
// mode 1: epilogue *kw, fp32 interleaved out (layer1)
// mode 2: epilogue tanh only, fp32 head-major out (layer0 core)
__global__ __launch_bounds__(128, 4)
void k_layer4h(const __half* __restrict__ xh, const float* __restrict__ kw,
               const float* __restrict__ r, float* __restrict__ xo_f, int mode) {
    __shared__ float  srd[4][3][DD];
    __shared__ __align__(16) __half sxh[4][3][4][DD];
    int warp = threadIdx.x >> 5, lane = threadIdx.x & 31;
    int v = blockIdx.x*4 + warp;
    bool on = lane < 25;
    int off = lane * 8;

    float xd[4][8], acc[4][8];
    float rm[4], rs[4];
    #pragma unroll
    for (int h = 0; h < 4; h++) {
        rm[h] = -INFINITY; rs[h] = 0.f;
        #pragma unroll
        for (int j = 0; j < 8; j++) { xd[h][j] = 0.f; acc[h][j] = 0.f; }
        if (on) {
            const __half2* p = (const __half2*)(xh + ((size_t)h*NN + v)*DD + off);
            #pragma unroll
            for (int q = 0; q < 4; q++) {
                float2 f = __half22float2(p[q]);
                xd[h][q*2] = f.x; xd[h][q*2+1] = f.y;
            }
        }
    }

    int e0 = g_rowptr[v], e1 = g_rowptr[v+1];

    auto issue = [&](int e) {
        int slot = e % 3;
        if (on) {
            int s  = g_csrc[e];
            int et = g_cet[e];
            const float* rg = r + (size_t)et*DD + off;
            float* rd = &srd[warp][slot][off];
            __pipeline_memcpy_async(rd,     rg,     16);
            __pipeline_memcpy_async(rd + 4, rg + 4, 16);
            #pragma unroll
            for (int h = 0; h < 4; h++) {
                const __half* xg = xh + ((size_t)h*NN + s)*DD + off;
                __half* xdst = &sxh[warp][slot][h][off];
                __pipeline_memcpy_async(xdst, xg, 16);
            }
        }
        __pipeline_commit();
    };

    if (e0     < e1) issue(e0);     else __pipeline_commit();
    if (e0 + 1 < e1) issue(e0 + 1); else __pipeline_commit();

    for (int e = e0; e < e1; ++e) {
        if (e + 2 < e1) issue(e + 2); else __pipeline_commit();
        __pipeline_wait_prior(2);
        int slot = e % 3;

        float xsr[4][8];
        float p[4] = {0.f, 0.f, 0.f, 0.f};
        if (on) {
            float rr[8];
            {
                const float4* rp = (const float4*)&srd[warp][slot][off];
                float4 a = rp[0], b = rp[1];
                rr[0]=a.x; rr[1]=a.y; rr[2]=a.z; rr[3]=a.w;
                rr[4]=b.x; rr[5]=b.y; rr[6]=b.z; rr[7]=b.w;
            }
            #pragma unroll
            for (int h = 0; h < 4; h++) {
                const __half2* xp = (const __half2*)&sxh[warp][slot][h][off];
                float sum = 0.f;
                #pragma unroll
                for (int q = 0; q < 4; q++) {
                    float2 f = __half22float2(xp[q]);
                    xsr[h][q*2]   = f.x * rr[q*2];
                    xsr[h][q*2+1] = f.y * rr[q*2+1];
                    sum += xsr[h][q*2]*xd[h][q*2] + xsr[h][q*2+1]*xd[h][q*2+1];
                }
                p[h] = sum;
            }
        } else {
            #pragma unroll
            for (int h = 0; h < 4; h++)
                #pragma unroll
                for (int j = 0; j < 8; j++) xsr[h][j] = 0.f;
        }
        #pragma unroll
        for (int o = 16; o > 0; o >>= 1) {
            p[0] += __shfl_xor_sync(0xffffffffu, p[0], o);
            p[1] += __shfl_xor_sync(0xffffffffu, p[1], o);
            p[2] += __shfl_xor_sync(0xffffffffu, p[2], o);
            p[3] += __shfl_xor_sync(0xffffffffu, p[3], o);
        }
        #pragma unroll
        for (int h = 0; h < 4; h++) {
            float dot = p[h];
            float l = (dot > 0.f) ? dot : 0.2f*dot;
            float nm = fmaxf(rm[h], l);
            float sc = (rm[h] == -INFINITY) ? 0.f : __expf(rm[h] - nm);
            float w = __expf(l - nm);
            rm[h] = nm; rs[h] = rs[h]*sc + w;
            #pragma unroll
            for (int j = 0; j < 8; j++)
                acc[h][j] = acc[h][j]*sc + w*xsr[h][j];
        }
    }
    if (!on) return;
    #pragma unroll
    for (int h = 0; h < 4; h++) {
        float inv = 1.f/(rs[h] + 1e-16f);
        float o[8];
        if (mode == 2) {
            #pragma unroll
            for (int j = 0; j < 8; j++) o[j] = tanhf(acc[h][j]*inv);
            float* w = xo_f + ((size_t)h*NN + v)*DD + off;
            __stcs((float4*)w,     make_float4(o[0], o[1], o[2], o[3]));
            __stcs((float4*)w + 1, make_float4(o[4], o[5], o[6], o[7]));
        } else {
            const float4* kwp = (const float4*)(kw + ((size_t)h*NN + v)*DD + off);
            float4 ka = __ldcs(kwp), kb = __ldcs(kwp+1);
            float kk[8] = {ka.x, ka.y, ka.z, ka.w, kb.x, kb.y, kb.z, kb.w};
            #pragma unroll
            for (int j = 0; j < 8; j++) o[j] = tanhf(acc[h][j]*inv) * kk[j];
            float* w = xo_f + (size_t)v*FD + (size_t)h*DD + off;
            __stcs((float4*)w,     make_float4(o[0], o[1], o[2], o[3]));
            __stcs((float4*)w + 1, make_float4(o[4], o[5], o[6], o[7]));
        }
    }
}

// ---------------- output gathers ----------------------------------------------
__global__ void k_subemb(const int* __restrict__ sub, const float* __restrict__ x,
                         float* __restrict__ o) {
    int b = blockIdx.x;
    int row = sub[b];
    for (int idx = threadIdx.x; idx < FD; idx += blockDim.x)
        o[(size_t)b*FD + idx] = x[(size_t)row*FD + idx];
}
__global__ void k_relemb(const int* __restrict__ rel, const float* __restrict__ ir,
                         float* __restrict__ o) {
    int b = blockIdx.x;
    int row = rel[b];
    for (int idx = threadIdx.x; idx < FD; idx += blockDim.x) {
        int d = idx % DD;
        o[(size_t)b*FD + idx] = ir[(size_t)row*DD + d];
    }
}

// ---------------- CLUB layer 1 (12 batched GEMMs, relu) ----------------------
__global__ void k_club1(const float* __restrict__ semb,
                        const float* __restrict__ mu_w1, const float* __restrict__ mu_b1,
                        const float* __restrict__ lv_w1, const float* __restrict__ lv_b1,
                        float* __restrict__ H) {
    const int ci[6] = {0,0,0,1,1,2};
    int z = blockIdx.z, cnt = z >> 1, net = z & 1;
    const float* A  = semb + ci[cnt]*DD;
    const float* W  = (net ? lv_w1 : mu_w1) + (size_t)cnt*DD*HH2;
    const float* bb = (net ? lv_b1 : mu_b1) + cnt*HH2;
    float* C = H + (size_t)z*BB*HH2;

    __shared__ float As[8][64];
    __shared__ float Bs[8][65];
    int tid = threadIdx.x;
    int tx = tid & 15, ty = tid >> 4;
    int row0 = blockIdx.x*64, col0 = blockIdx.y*64;
    float acc[4][4] = {};
    for (int k0 = 0; k0 < DD; k0 += 8) {
        #pragma unroll
        for (int i = 0; i < 2; i++) {
            int idx = tid*2 + i;
            int rI = idx >> 3, kk = idx & 7;
            As[kk][rI] = A[(size_t)(row0+rI)*FD + k0 + kk];
        }
        #pragma unroll
        for (int i = 0; i < 2; i++) {
            int idx = tid + i*256;
            int kk = idx >> 6, c = idx & 63;
            int gc = col0 + c;
            Bs[kk][c] = (gc < HH2) ? W[(size_t)(k0+kk)*HH2 + gc] : 0.f;
        }
        __syncthreads();
        #pragma unroll
        for (int kk = 0; kk < 8; kk++) {
            float a[4], b[4];
            #pragma unroll
            for (int i = 0; i < 4; i++) a[i] = As[kk][ty*4+i];
            #pragma unroll
            for (int j = 0; j < 4; j++) b[j] = Bs[kk][tx*4+j];
            #pragma unroll
            for (int i = 0; i < 4; i++)
                #pragma unroll
                for (int j = 0; j < 4; j++)
                    acc[i][j] += a[i]*b[j];
        }
        __syncthreads();
    }
    #pragma unroll
    for (int i = 0; i < 4; i++) {
        int gr = row0 + ty*4 + i;
        #pragma unroll
        for (int j = 0; j < 4; j++) {
            int gc = col0 + tx*4 + j;
            if (gc < HH2)
                C[(size_t)gr*HH2 + gc] = fmaxf(acc[i][j] + bb[gc], 0.f);
        }
    }
}

// ---------------- CLUB layer 2 as batched GEMM (z = pair*2 + net) -----------
__global__ __launch_bounds__(128, 4)
void k_club2g(const float* __restrict__ mu_w2, const float* __restrict__ mu_b2,
              const float* __restrict__ lv_w2, const float* __restrict__ lv_b2) {
    __shared__ __align__(16) float As[2][16][128];
    __shared__ __align__(16) float Bs[2][16][64];
    int z = blockIdx.z, cnt = z >> 1, net = z & 1;
    const float* A  = g_h + (size_t)z*BB*HH2;
    const float* W  = (net ? lv_w2 : mu_w2) + (size_t)cnt*HH2*DD;
    const float* bb = (net ? lv_b2 : mu_b2) + cnt*DD;
    float* C = g_o2 + (size_t)z*BB*DD;
    const int N = DD, K = HH2;
    int tid = threadIdx.x;
    int tx = tid & 7, ty = tid >> 3;
    int row0 = blockIdx.x*128, col0 = blockIdx.y*64;
    int bk = tid >> 3, bc = (tid & 7) * 8;

    u64t acc[4][8];
    #pragma unroll
    for (int i = 0; i < 4; i++)
        #pragma unroll
        for (int j = 0; j < 8; j++) acc[i][j] = 0ull;

    float pa[16], pb[8];
    int nkt = (K + 15) >> 4;
    #pragma unroll 1
    for (int kt = -1; kt < nkt; kt++) {
        if (kt + 1 < nkt) {
            int k0 = (kt + 1) * 16;
            int gr = row0 + tid;
            #pragma unroll
            for (int c = 0; c < 16; c++)
                pa[c] = (k0 + c < K) ? A[(size_t)gr*HH2 + k0 + c] : 0.f;
            #pragma unroll
            for (int c = 0; c < 8; c++) {
                int gc = col0 + bc + c;
                pb[c] = (k0 + bk < K && gc < N) ? W[(size_t)(k0+bk)*DD + gc] : 0.f;
            }
        }
        if (kt >= 0) {
            int cur = kt & 1;
            #pragma unroll
            for (int kk = 0; kk < 16; kk++) {
                const ulonglong2* ap2 = (const ulonglong2*)&As[cur][kk][ty*8];
                ulonglong2 aA = ap2[0];
                ulonglong2 aB = ap2[1];
                float4 bv0 = *(const float4*)&Bs[cur][kk][tx*8];
                float4 bv1 = *(const float4*)&Bs[cur][kk][tx*8+4];
                u64t b[8];
                b[0]=dup2(bv0.x); b[1]=dup2(bv0.y); b[2]=dup2(bv0.z); b[3]=dup2(bv0.w);
                b[4]=dup2(bv1.x); b[5]=dup2(bv1.y); b[6]=dup2(bv1.z); b[7]=dup2(bv1.w);
                #pragma unroll
                for (int j = 0; j < 8; j++) {
                    ffma2(acc[0][j], aA.x, b[j]);
                    ffma2(acc[1][j], aA.y, b[j]);
                    ffma2(acc[2][j], aB.x, b[j]);
                    ffma2(acc[3][j], aB.y, b[j]);
                }
            }
        }
        if (kt + 1 < nkt) {
            int nxt = (kt + 1) & 1;
            #pragma unroll
            for (int c = 0; c < 16; c++) As[nxt][c][tid] = pa[c];
            *(float4*)&Bs[nxt][bk][bc]   = make_float4(pb[0],pb[1],pb[2],pb[3]);
            *(float4*)&Bs[nxt][bk][bc+4] = make_float4(pb[4],pb[5],pb[6],pb[7]);
        }
        __syncthreads();
    }
    #pragma unroll
    for (int i = 0; i < 4; i++) {
        int r0 = row0 + ty*8 + i*2;
        #pragma unroll
        for (int j = 0; j < 8; j++) {
            int gc = col0 + tx*8 + j;
            if (gc >= N) continue;
            float2 p = unpack2(acc[i][j]);
            float bv = bb[gc];
            float v0 = p.x + bv, v1 = p.y + bv;
            if (net) { v0 = tanhf(v0); v1 = tanhf(v1); }
            C[(size_t)r0    *DD + gc] = v0;
            C[(size_t)(r0+1)*DD + gc] = v1;
        }
    }
}

// ---------------- loss reduction ----------------------------------------------
__global__ void k_loss(const float* __restrict__ semb, const int* __restrict__ perm,
                       float* __restrict__ mi) {
    const int cj[6] = {1,2,3,2,3,3};
    int b = blockIdx.x, cnt = blockIdx.y;
    __shared__ float red[256];
    int tid = threadIdx.x;
    float c = 0.f;
    if (tid < DD) {
        float mu = g_o2[((size_t)(cnt*2+0)*BB + b)*DD + tid];
        float lv = g_o2[((size_t)(cnt*2+1)*BB + b)*DD + tid];
        int j = cj[cnt];
        float yj  = semb[(size_t)b*FD + j*DD + tid];
        float yjp = semb[(size_t)perm[b]*FD + j*DD + tid];
        float d1 = mu - yj, d2 = mu - yjp;
        c = (d2*d2 - d1*d1) * expf(-lv);
    }
    red[tid] = c; __syncthreads();
    for (int o = 128; o > 0; o >>= 1) {
        if (tid < o) red[tid] += red[tid+o];
        __syncthreads();
    }
    if (tid == 0) atomicAdd(mi, red[0] * (0.5f/BB));
}

// ---------------- launch --------------------------------------------------------
extern "C" void kernel_launch(void* const* d_in, const int* in_sizes, int n_in,
                              void* d_out, int out_size) {
    const int*   sub        = (const int*)  d_in[0];
    const int*   rel        = (const int*)  d_in[1];
    const int*   eidx       = (const int*)  d_in[2];
    const int*   etype      = (const int*)  d_in[3];
    const int*   perm       = (const int*)  d_in[4];
    const float* init_embed = (const float*)d_in[5];
    const float* init_rel   = (const float*)d_in[6];
    const float* pca_w      = (const float*)d_in[7];
    const float* pca_b      = (const float*)d_in[8];
    const float* cw_w       = (const float*)d_in[9];
    const float* w_rel      = (const float*)d_in[10];
    const float* mu_w1      = (const float*)d_in[11];
    const float* mu_b1      = (const float*)d_in[12];
    const float* mu_w2      = (const float*)d_in[13];
    const float* mu_b2      = (const float*)d_in[14];
    const float* lv_w1      = (const float*)d_in[15];
    const float* lv_b1      = (const float*)d_in[16];
    const float* lv_w2      = (const float*)d_in[17];
    const float* lv_b2      = (const float*)d_in[18];
    float* out = (float*)d_out;

    const int* src = eidx;
    const int* dst = eidx + EE;

    float *xA, *xB, *kw, *r1, *H, *th0;
    __half *xhA, *xhB;
    cudaGetSymbolAddress((void**)&xA, g_xA);
    cudaGetSymbolAddress((void**)&xB, g_xB);
    cudaGetSymbolAddress((void**)&kw, g_kw);
    cudaGetSymbolAddress((void**)&r1, g_r1);
    cudaGetSymbolAddress((void**)&H, g_h);
    cudaGetSymbolAddress((void**)&th0, g_th0);
    cudaGetSymbolAddress((void**)&xhA, g_xhA);
    cudaGetSymbolAddress((void**)&xhB, g_xhB);

    const int NB = (NN + 255)/256;

    cudaStream_t s2, s3;
    cudaStreamCreate(&s2);
    cudaStreamCreate(&s3);
    cudaEvent_t evFork, evX, evCSR, evJoin, evL0;
    cudaEventCreateWithFlags(&evFork, cudaEventDisableTiming);
    cudaEventCreateWithFlags(&evX,    cudaEventDisableTiming);
    cudaEventCreateWithFlags(&evCSR,  cudaEventDisableTiming);
    cudaEventCreateWithFlags(&evJoin, cudaEventDisableTiming);
    cudaEventCreateWithFlags(&evL0,   cudaEventDisableTiming);

    cudaEventRecord(evFork, 0);
    cudaStreamWaitEvent(s2, evFork, 0);

    // ---- s2: CSR build -> evCSR -> r1 + rel_emb -> evJoin ----
    k_zero<<<NB, 256, 0, s2>>>(out + MI_OFF);
    k_hist<<<(EE + 255)/256, 256, 0, s2>>>(dst);
    k_scan1<<<NB, 256, 0, s2>>>();
    k_scan2<<<1, 256, 0, s2>>>(NB);
    k_scan3<<<NB, 256, 0, s2>>>();
    k_fill<<<(EE + 255)/256, 256, 0, s2>>>(src, dst, etype);
    cudaEventRecord(evCSR, s2);
    {
        dim3 g((NRELD + 127)/128, (DD + 63)/64);
        k_sgemm4<<<g, 128, 0, s2>>>(init_rel, DD, w_rel, DD, nullptr, r1, DD,
                                    nullptr, NRELD, DD, DD, 0, 0);
    }
    k_relemb<<<BB, 256, 0, s2>>>(rel, init_rel, out + REL_OFF);
    cudaEventRecord(evJoin, s2);

    // ---- s0: x0 GEMM -> evX; then kw GEMM + kwsm ----
    {
        dim3 g((NN + 127)/128, (FD + 63)/64);
        k_sgemm4<<<g, 128>>>(init_embed, INITD, pca_w, FD, pca_b, xA, FD,
                             xhA, NN, FD, INITD, 1, 1);
    }
    cudaEventRecord(evX, 0);
    {
        dim3 g((NN*FF + 127)/128, (DD + 63)/64);
        k_sgemm4<<<g, 128>>>(xA, DD, cw_w, DD, nullptr, xB, DD,
                             nullptr, NN*FF, DD, DD, 2, 0);
    }
    k_kwsm<<<(NN*DD + 255)/256, 256>>>(xB, kw);

    // ---- s3: layer0 core (overlaps kw GEMM) ----
    cudaStreamWaitEvent(s3, evX, 0);
    cudaStreamWaitEvent(s3, evCSR, 0);
    k_layer4h<<<NN/4, 128, 0, s3>>>(xhA, nullptr, init_rel, th0, 2);
    cudaEventRecord(evL0, s3);

    // ---- s0: join, mulkw, layer1, tail ----
    cudaStreamWaitEvent(0, evL0, 0);
    cudaStreamWaitEvent(0, evJoin, 0);
    k_mulkw<<<(NN*FD/2 + 255)/256, 256>>>(th0, kw, xhB);
    k_layer4h<<<NN/4, 128>>>(xhB, kw, r1, out + X_OFF, 1);

    k_subemb<<<BB, 256>>>(sub, out + X_OFF, out + SUB_OFF);
    {
        dim3 g(BB/64, (HH2 + 63)/64, 12);
        k_club1<<<g, 256>>>(out + SUB_OFF, mu_w1, mu_b1, lv_w1, lv_b1, H);
    }
    {
        dim3 g(BB/128, (DD + 63)/64, 12);
        k_club2g<<<g, 128>>>(mu_w2, mu_b2, lv_w2, lv_b2);
    }
    {
        dim3 g(BB, NPAIR);
        k_loss<<<g, 256>>>(out + SUB_OFF, perm, out + MI_OFF);
    }

    cudaEventDestroy(evFork);
    cudaEventDestroy(evX);
    cudaEventDestroy(evCSR);
    cudaEventDestroy(evJoin);
    cudaEventDestroy(evL0);
    cudaStreamDestroy(s2);
    cudaStreamDestroy(s3);
}

// round 16
// speedup vs baseline: 1.0088x; 1.0088x over previous
#include <cuda_runtime.h>
#include <cuda_pipeline.h>
#include <cuda_fp16.h>
#include <math.h>
#include <stdint.h>

#define NN    40000
#define INITD 100
#define DD    200
#define FF    4
#define EE    800000
#define NRELD 800
#define BB    2048
#define HH2   100
#define NPAIR 6
#define FD    (FF*DD)   // 800

#define SUB_OFF 0
#define REL_OFF ((size_t)BB*FD)
#define X_OFF   ((size_t)2*BB*FD)
#define MI_OFF  ((size_t)2*BB*FD + (size_t)NN*FD)

typedef unsigned long long u64t;

// ---------------- scratch ----------------------------------------------------
__device__ float g_xA[(size_t)NN*FD];   // head-major fp32 (kw GEMM input)
__device__ float g_xB[(size_t)NN*FD];   // kw_raw temp
__device__ float g_kw[(size_t)NN*FD];
__device__ __align__(16) __half g_xhA[(size_t)NN*FD];  // fp16 x0 (layer0 gather)
__device__ __align__(16) __half g_xhB[(size_t)NN*FD];  // fp16 layer0 out (layer1 gather)
__device__ float g_r1[NRELD*DD];
__device__ float g_h[12*BB*HH2];
__device__ float g_o2[12*BB*DD];
__device__ int   g_deg[NN];
__device__ int   g_cur[NN];
__device__ int   g_rowptr[NN+1];
__device__ int   g_csrc[EE];
__device__ int   g_cet[EE];
__device__ int   g_bsums[256];
__device__ int   g_boffs[256];

// ---------------- packed f32x2 helpers ---------------------------------------
__device__ __forceinline__ void ffma2(u64t& d, u64t a, u64t b) {
    asm("fma.rn.f32x2 %0, %1, %2, %0;" : "+l"(d) : "l"(a), "l"(b));
}
__device__ __forceinline__ u64t dup2(float x) {
    u64t r; asm("mov.b64 %0, {%1, %2};" : "=l"(r) : "f"(x), "f"(x)); return r;
}
__device__ __forceinline__ float2 unpack2(u64t v) {
    float lo, hi; asm("mov.b64 {%0, %1}, %2;" : "=f"(lo), "=f"(hi) : "l"(v));
    return make_float2(lo, hi);
}

// ---------------- CSR build ---------------------------------------------------
__global__ void k_zero(float* mi) {
    int i = blockIdx.x*blockDim.x + threadIdx.x;
    if (i < NN) { g_deg[i] = 0; g_cur[i] = 0; }
    if (i == 0) *mi = 0.f;
}
__global__ void k_hist(const int* __restrict__ dst) {
    int e = blockIdx.x*blockDim.x + threadIdx.x;
    if (e < EE) atomicAdd(&g_deg[dst[e]], 1);
}
__global__ void k_scan1() {
    __shared__ int s[256];
    int tid = threadIdx.x;
    int i = blockIdx.x*256 + tid;
    int v = (i < NN) ? g_deg[i] : 0;
    s[tid] = v; __syncthreads();
    for (int off = 1; off < 256; off <<= 1) {
        int t = (tid >= off) ? s[tid-off] : 0;
        __syncthreads(); s[tid] += t; __syncthreads();
    }
    if (i < NN) g_rowptr[i] = s[tid] - v;
    if (tid == 255) g_bsums[blockIdx.x] = s[255];
}
__global__ void k_scan2(int nb) {
    __shared__ int s[256];
    int tid = threadIdx.x;
    int v = (tid < nb) ? g_bsums[tid] : 0;
    s[tid] = v; __syncthreads();
    for (int off = 1; off < 256; off <<= 1) {
        int t = (tid >= off) ? s[tid-off] : 0;
        __syncthreads(); s[tid] += t; __syncthreads();
    }
    if (tid < nb) g_boffs[tid] = s[tid] - v;
}
__global__ void k_scan3() {
    int tid = threadIdx.x;
    int i = blockIdx.x*256 + tid;
    if (i < NN) g_rowptr[i] += g_boffs[blockIdx.x];
    if (i == 0) g_rowptr[NN] = EE;
}
__global__ void k_fill(const int* __restrict__ src, const int* __restrict__ dst,
                       const int* __restrict__ et) {
    int e = blockIdx.x*blockDim.x + threadIdx.x;
    if (e >= EE) return;
    int d = dst[e];
    int pos = g_rowptr[d] + atomicAdd(&g_cur[d], 1);
    g_csrc[pos] = src[e];
    g_cet[pos]  = et[e];
}

// ---------------- SGEMM v5: 128x64, coalesced A, f32x2 ----------------------
__global__ __launch_bounds__(128, 4)
void k_sgemm4(const float* __restrict__ A, int lda,
              const float* __restrict__ B, int ldb,
              const float* __restrict__ bias,
              float* __restrict__ C, int ldc,
              __half* __restrict__ Ch,
              int M, int N, int K, int act, int hm) {
    __shared__ __align__(16) float As[2][16][128];
    __shared__ __align__(16) float Bs[2][16][64];
    int tid = threadIdx.x;
    int tx = tid & 7, ty = tid >> 3;
    int row0 = blockIdx.x*128, col0 = blockIdx.y*64;
    int bk = tid >> 3, bc = (tid & 7) * 8;
    int arow = tid >> 2;
    int ak4  = (tid & 3) * 4;

    u64t acc[4][8];
    #pragma unroll
    for (int i = 0; i < 4; i++)
        #pragma unroll
        for (int j = 0; j < 8; j++) acc[i][j] = 0ull;

    float pa[16], pb[8];
    int nkt = (K + 15) >> 4;
    #pragma unroll 1
    for (int kt = -1; kt < nkt; kt++) {
        bool fastA = false;
        if (kt + 1 < nkt) {
            int k0 = (kt + 1) * 16;
            fastA = (k0 + 16 <= K) && (row0 + 128 <= M);
            if (fastA) {
                #pragma unroll
                for (int it = 0; it < 4; it++) {
                    float4 v = *(const float4*)(A + (size_t)(row0 + arow + it*32)*lda + k0 + ak4);
                    pa[it*4+0] = v.x; pa[it*4+1] = v.y; pa[it*4+2] = v.z; pa[it*4+3] = v.w;
                }
            } else {
                int gr = row0 + tid;
                #pragma unroll
                for (int c = 0; c < 16; c++)
                    pa[c] = (gr < M && k0 + c < K) ? A[(size_t)gr*lda + k0 + c] : 0.f;
            }
            if (k0 + bk < K && col0 + 64 <= N) {
                const float* bp = B + (size_t)(k0 + bk)*ldb + col0 + bc;
                float4 v0=*(const float4*)bp, v1=*(const float4*)(bp+4);
                pb[0]=v0.x;pb[1]=v0.y;pb[2]=v0.z;pb[3]=v0.w;
                pb[4]=v1.x;pb[5]=v1.y;pb[6]=v1.z;pb[7]=v1.w;
            } else {
                #pragma unroll
                for (int c = 0; c < 8; c++) {
                    int gc = col0 + bc + c;
                    pb[c] = (k0 + bk < K && gc < N) ? B[(size_t)(k0+bk)*ldb + gc] : 0.f;
                }
            }
        }
        if (kt >= 0) {
            int cur = kt & 1;
            #pragma unroll
            for (int kk = 0; kk < 16; kk++) {
                const ulonglong2* ap2 = (const ulonglong2*)&As[cur][kk][ty*8];
                ulonglong2 aA = ap2[0];
                ulonglong2 aB = ap2[1];
                float4 bv0 = *(const float4*)&Bs[cur][kk][tx*8];
                float4 bv1 = *(const float4*)&Bs[cur][kk][tx*8+4];
                u64t b[8];
                b[0]=dup2(bv0.x); b[1]=dup2(bv0.y); b[2]=dup2(bv0.z); b[3]=dup2(bv0.w);
                b[4]=dup2(bv1.x); b[5]=dup2(bv1.y); b[6]=dup2(bv1.z); b[7]=dup2(bv1.w);
                #pragma unroll
                for (int j = 0; j < 8; j++) {
                    ffma2(acc[0][j], aA.x, b[j]);
                    ffma2(acc[1][j], aA.y, b[j]);
                    ffma2(acc[2][j], aB.x, b[j]);
                    ffma2(acc[3][j], aB.y, b[j]);
                }
            }
        }
        if (kt + 1 < nkt) {
            int nxt = (kt + 1) & 1;
            if (fastA) {
                #pragma unroll
                for (int it = 0; it < 4; it++) {
                    int rr = arow + it*32;
                    As[nxt][ak4+0][rr] = pa[it*4+0];
                    As[nxt][ak4+1][rr] = pa[it*4+1];
                    As[nxt][ak4+2][rr] = pa[it*4+2];
                    As[nxt][ak4+3][rr] = pa[it*4+3];
                }
            } else {
                #pragma unroll
                for (int c = 0; c < 16; c++) As[nxt][c][tid] = pa[c];
            }
            *(float4*)&Bs[nxt][bk][bc]   = make_float4(pb[0],pb[1],pb[2],pb[3]);
            *(float4*)&Bs[nxt][bk][bc+4] = make_float4(pb[4],pb[5],pb[6],pb[7]);
        }
        __syncthreads();
    }

    #pragma unroll
    for (int i = 0; i < 4; i++) {
        int r0 = row0 + ty*8 + i*2;
        #pragma unroll
        for (int j = 0; j < 8; j++) {
            int gc = col0 + tx*8 + j;
            if (gc >= N) continue;
            float2 p = unpack2(acc[i][j]);
            float bv = bias ? bias[gc] : 0.f;
            float v0 = p.x + bv, v1 = p.y + bv;
            if (act == 1) { v0 = tanhf(v0); v1 = tanhf(v1); }
            else if (act == 2) { v0 = (v0 > 0.f) ? v0 : 0.2f*v0; v1 = (v1 > 0.f) ? v1 : 0.2f*v1; }
            if (hm) {
                int f = gc / DD, d = gc - f*DD;
                size_t base = (size_t)f*NN*DD + d;
                if (r0 < M) {
                    C[base + (size_t)r0*DD] = v0;
                    if (Ch) Ch[base + (size_t)r0*DD] = __float2half(v0);
                }
                if (r0 + 1 < M) {
                    C[base + (size_t)(r0+1)*DD] = v1;
                    if (Ch) Ch[base + (size_t)(r0+1)*DD] = __float2half(v1);
                }
            } else {
                if (r0     < M) C[(size_t)r0    *ldc + gc] = v0;
                if (r0 + 1 < M) C[(size_t)(r0+1)*ldc + gc] = v1;
            }
        }
    }
}

// ---------------- kw softmax over F axis (head-major) ------------------------
__global__ void k_kwsm(const float* __restrict__ raw, float* __restrict__ kw) {
    int i = blockIdx.x*blockDim.x + threadIdx.x;
    if (i >= NN*DD) return;
    const float* p = raw + i;
    const size_t S = (size_t)NN*DD;
    float a0 = __ldcs(p), a1 = __ldcs(p+S), a2 = __ldcs(p+2*S), a3 = __ldcs(p+3*S);
    float m = fmaxf(fmaxf(a0, a1), fmaxf(a2, a3));
    float e0 = __expf(a0-m), e1 = __expf(a1-m), e2 = __expf(a2-m), e3 = __expf(a3-m);
    float inv = 1.f/(e0+e1+e2+e3);
    float* q = kw + i;
    __stcs(q, e0*inv); __stcs(q+S, e1*inv); __stcs(q+2*S, e2*inv); __stcs(q+3*S, e3*inv);
}

// ---------------- attention layer: fp16 gathers, cp.async 4-slot ring --------
// mode 0: write fp16 head-major to xo_h. mode 1: write fp32 interleaved to xo_f.
__global__ __launch_bounds__(128, 4)
void k_layer4h(const __half* __restrict__ xh, const float* __restrict__ kw,
               const float* __restrict__ r, float* __restrict__ xo_f,
               __half* __restrict__ xo_h, int mode) {
    __shared__ float  srd[4][4][DD];
    __shared__ __align__(16) __half sxh[4][4][4][DD];
    int warp = threadIdx.x >> 5, lane = threadIdx.x & 31;
    int v = blockIdx.x*4 + warp;
    bool on = lane < 25;
    int off = lane * 8;

    float xd[4][8], acc[4][8];
    float rm[4], rs[4];
    #pragma unroll
    for (int h = 0; h < 4; h++) {
        rm[h] = -INFINITY; rs[h] = 0.f;
        #pragma unroll
        for (int j = 0; j < 8; j++) { xd[h][j] = 0.f; acc[h][j] = 0.f; }
        if (on) {
            const __half2* p = (const __half2*)(xh + ((size_t)h*NN + v)*DD + off);
            #pragma unroll
            for (int q = 0; q < 4; q++) {
                float2 f = __half22float2(p[q]);
                xd[h][q*2] = f.x; xd[h][q*2+1] = f.y;
            }
        }
    }

    int e0 = g_rowptr[v], e1 = g_rowptr[v+1];

    auto issue = [&](int e) {
        int slot = e & 3;
        if (on) {
            int s  = g_csrc[e];
            int et = g_cet[e];
            const float* rg = r + (size_t)et*DD + off;
            float* rd = &srd[warp][slot][off];
            __pipeline_memcpy_async(rd,     rg,     16);
            __pipeline_memcpy_async(rd + 4, rg + 4, 16);
            #pragma unroll
            for (int h = 0; h < 4; h++) {
                const __half* xg = xh + ((size_t)h*NN + s)*DD + off;
                __half* xdst = &sxh[warp][slot][h][off];
                __pipeline_memcpy_async(xdst, xg, 16);
            }
        }
        __pipeline_commit();
    };

    // prologue: 3 committed groups ahead
    if (e0     < e1) issue(e0);     else __pipeline_commit();
    if (e0 + 1 < e1) issue(e0 + 1); else __pipeline_commit();
    if (e0 + 2 < e1) issue(e0 + 2); else __pipeline_commit();

    for (int e = e0; e < e1; ++e) {
        if (e + 3 < e1) issue(e + 3); else __pipeline_commit();
        __pipeline_wait_prior(3);
        int slot = e & 3;

        float xsr[4][8];
        float p[4] = {0.f, 0.f, 0.f, 0.f};
        if (on) {
            float rr[8];
            {
                const float4* rp = (const float4*)&srd[warp][slot][off];
                float4 a = rp[0], b = rp[1];
                rr[0]=a.x; rr[1]=a.y; rr[2]=a.z; rr[3]=a.w;
                rr[4]=b.x; rr[5]=b.y; rr[6]=b.z; rr[7]=b.w;
            }
            #pragma unroll
            for (int h = 0; h < 4; h++) {
                const __half2* xp = (const __half2*)&sxh[warp][slot][h][off];
                float sum = 0.f;
                #pragma unroll
                for (int q = 0; q < 4; q++) {
                    float2 f = __half22float2(xp[q]);
                    xsr[h][q*2]   = f.x * rr[q*2];
                    xsr[h][q*2+1] = f.y * rr[q*2+1];
                    sum += xsr[h][q*2]*xd[h][q*2] + xsr[h][q*2+1]*xd[h][q*2+1];
                }
                p[h] = sum;
            }
        } else {
            #pragma unroll
            for (int h = 0; h < 4; h++)
                #pragma unroll
                for (int j = 0; j < 8; j++) xsr[h][j] = 0.f;
        }
        #pragma unroll
        for (int o = 16; o > 0; o >>= 1) {
            p[0] += __shfl_xor_sync(0xffffffffu, p[0], o);
            p[1] += __shfl_xor_sync(0xffffffffu, p[1], o);
            p[2] += __shfl_xor_sync(0xffffffffu, p[2], o);
            p[3] += __shfl_xor_sync(0xffffffffu, p[3], o);
        }
        #pragma unroll
        for (int h = 0; h < 4; h++) {
            float dot = p[h];
            float l = (dot > 0.f) ? dot : 0.2f*dot;
            float nm = fmaxf(rm[h], l);
            float sc = (rm[h] == -INFINITY) ? 0.f : __expf(rm[h] - nm);
            float w = __expf(l - nm);
            rm[h] = nm; rs[h] = rs[h]*sc + w;
            #pragma unroll
            for (int j = 0; j < 8; j++)
                acc[h][j] = acc[h][j]*sc + w*xsr[h][j];
        }
    }
    if (!on) return;
    #pragma unroll
    for (int h = 0; h < 4; h++) {
        float inv = 1.f/(rs[h] + 1e-16f);
        const float4* kwp = (const float4*)(kw + ((size_t)h*NN + v)*DD + off);
        float4 ka = __ldcs(kwp), kb = __ldcs(kwp+1);
        float kk[8] = {ka.x, ka.y, ka.z, ka.w, kb.x, kb.y, kb.z, kb.w};
        float o[8];
        #pragma unroll
        for (int j = 0; j < 8; j++) o[j] = tanhf(acc[h][j]*inv) * kk[j];
        if (mode == 0) {
            __half2 h2[4];
            #pragma unroll
            for (int q = 0; q < 4; q++) h2[q] = __floats2half2_rn(o[q*2], o[q*2+1]);
            *(uint4*)(xo_h + ((size_t)h*NN + v)*DD + off) = *(uint4*)h2;
        } else {
            float* w = xo_f + (size_t)v*FD + (size_t)h*DD + off;
            __stcs((float4*)w,     make_float4(o[0], o[1], o[2], o[3]));
            __stcs((float4*)w + 1, make_float4(o[4], o[5], o[6], o[7]));
        }
    }
}

// ---------------- output gathers ----------------------------------------------
__global__ void k_subemb(const int* __restrict__ sub, const float* __restrict__ x,
                         float* __restrict__ o) {
    int b = blockIdx.x;
    int row = sub[b];
    for (int idx = threadIdx.x; idx < FD; idx += blockDim.x)
        o[(size_t)b*FD + idx] = x[(size_t)row*FD + idx];
}
__global__ void k_relemb(const int* __restrict__ rel, const float* __restrict__ ir,
                         float* __restrict__ o) {
    int b = blockIdx.x;
    int row = rel[b];
    for (int idx = threadIdx.x; idx < FD; idx += blockDim.x) {
        int d = idx % DD;
        o[(size_t)b*FD + idx] = ir[(size_t)row*DD + d];
    }
}

// ---------------- CLUB layer 1 (12 batched GEMMs, relu) ----------------------
__global__ void k_club1(const float* __restrict__ semb,
                        const float* __restrict__ mu_w1, const float* __restrict__ mu_b1,
                        const float* __restrict__ lv_w1, const float* __restrict__ lv_b1,
                        float* __restrict__ H) {
    const int ci[6] = {0,0,0,1,1,2};
    int z = blockIdx.z, cnt = z >> 1, net = z & 1;
    const float* A  = semb + ci[cnt]*DD;
    const float* W  = (net ? lv_w1 : mu_w1) + (size_t)cnt*DD*HH2;
    const float* bb = (net ? lv_b1 : mu_b1) + cnt*HH2;
    float* C = H + (size_t)z*BB*HH2;

    __shared__ float As[8][64];
    __shared__ float Bs[8][65];
    int tid = threadIdx.x;
    int tx = tid & 15, ty = tid >> 4;
    int row0 = blockIdx.x*64, col0 = blockIdx.y*64;
    float acc[4][4] = {};
    for (int k0 = 0; k0 < DD; k0 += 8) {
        #pragma unroll
        for (int i = 0; i < 2; i++) {
            int idx = tid*2 + i;
            int rI = idx >> 3, kk = idx & 7;
            As[kk][rI] = A[(size_t)(row0+rI)*FD + k0 + kk];
        }
        #pragma unroll
        for (int i = 0; i < 2; i++) {
            int idx = tid + i*256;
            int kk = idx >> 6, c = idx & 63;
            int gc = col0 + c;
            Bs[kk][c] = (gc < HH2) ? W[(size_t)(k0+kk)*HH2 + gc] : 0.f;
        }
        __syncthreads();
        #pragma unroll
        for (int kk = 0; kk < 8; kk++) {
            float a[4], b[4];
            #pragma unroll
            for (int i = 0; i < 4; i++) a[i] = As[kk][ty*4+i];
            #pragma unroll
            for (int j = 0; j < 4; j++) b[j] = Bs[kk][tx*4+j];
            #pragma unroll
            for (int i = 0; i < 4; i++)
                #pragma unroll
                for (int j = 0; j < 4; j++)
                    acc[i][j] += a[i]*b[j];
        }
        __syncthreads();
    }
    #pragma unroll
    for (int i = 0; i < 4; i++) {
        int gr = row0 + ty*4 + i;
        #pragma unroll
        for (int j = 0; j < 4; j++) {
            int gc = col0 + tx*4 + j;
            if (gc < HH2)
                C[(size_t)gr*HH2 + gc] = fmaxf(acc[i][j] + bb[gc], 0.f);
        }
    }
}

// ---------------- CLUB layer 2 as batched GEMM (z = pair*2 + net) -----------
__global__ __launch_bounds__(128, 4)
void k_club2g(const float* __restrict__ mu_w2, const float* __restrict__ mu_b2,
              const float* __restrict__ lv_w2, const float* __restrict__ lv_b2) {
    __shared__ __align__(16) float As[2][16][128];
    __shared__ __align__(16) float Bs[2][16][64];
    int z = blockIdx.z, cnt = z >> 1, net = z & 1;
    const float* A  = g_h + (size_t)z*BB*HH2;
    const float* W  = (net ? lv_w2 : mu_w2) + (size_t)cnt*HH2*DD;
    const float* bb = (net ? lv_b2 : mu_b2) + cnt*DD;
    float* C = g_o2 + (size_t)z*BB*DD;
    const int N = DD, K = HH2;
    int tid = threadIdx.x;
    int tx = tid & 7, ty = tid >> 3;
    int row0 = blockIdx.x*128, col0 = blockIdx.y*64;
    int bk = tid >> 3, bc = (tid & 7) * 8;

    u64t acc[4][8];
    #pragma unroll
    for (int i = 0; i < 4; i++)
        #pragma unroll
        for (int j = 0; j < 8; j++) acc[i][j] = 0ull;

    float pa[16], pb[8];
    int nkt = (K + 15) >> 4;
    #pragma unroll 1
    for (int kt = -1; kt < nkt; kt++) {
        if (kt + 1 < nkt) {
            int k0 = (kt + 1) * 16;
            int gr = row0 + tid;
            #pragma unroll
            for (int c = 0; c < 16; c++)
                pa[c] = (k0 + c < K) ? A[(size_t)gr*HH2 + k0 + c] : 0.f;
            #pragma unroll
            for (int c = 0; c < 8; c++) {
                int gc = col0 + bc + c;
                pb[c] = (k0 + bk < K && gc < N) ? W[(size_t)(k0+bk)*DD + gc] : 0.f;
            }
        }
        if (kt >= 0) {
            int cur = kt & 1;
            #pragma unroll
            for (int kk = 0; kk < 16; kk++) {
                const ulonglong2* ap2 = (const ulonglong2*)&As[cur][kk][ty*8];
                ulonglong2 aA = ap2[0];
                ulonglong2 aB = ap2[1];
                float4 bv0 = *(const float4*)&Bs[cur][kk][tx*8];
                float4 bv1 = *(const float4*)&Bs[cur][kk][tx*8+4];
                u64t b[8];
                b[0]=dup2(bv0.x); b[1]=dup2(bv0.y); b[2]=dup2(bv0.z); b[3]=dup2(bv0.w);
                b[4]=dup2(bv1.x); b[5]=dup2(bv1.y); b[6]=dup2(bv1.z); b[7]=dup2(bv1.w);
                #pragma unroll
                for (int j = 0; j < 8; j++) {
                    ffma2(acc[0][j], aA.x, b[j]);
                    ffma2(acc[1][j], aA.y, b[j]);
                    ffma2(acc[2][j], aB.x, b[j]);
                    ffma2(acc[3][j], aB.y, b[j]);
                }
            }
        }
        if (kt + 1 < nkt) {
            int nxt = (kt + 1) & 1;
            #pragma unroll
            for (int c = 0; c < 16; c++) As[nxt][c][tid] = pa[c];
            *(float4*)&Bs[nxt][bk][bc]   = make_float4(pb[0],pb[1],pb[2],pb[3]);
            *(float4*)&Bs[nxt][bk][bc+4] = make_float4(pb[4],pb[5],pb[6],pb[7]);
        }
        __syncthreads();
    }
    #pragma unroll
    for (int i = 0; i < 4; i++) {
        int r0 = row0 + ty*8 + i*2;
        #pragma unroll
        for (int j = 0; j < 8; j++) {
            int gc = col0 + tx*8 + j;
            if (gc >= N) continue;
            float2 p = unpack2(acc[i][j]);
            float bv = bb[gc];
            float v0 = p.x + bv, v1 = p.y + bv;
            if (net) { v0 = tanhf(v0); v1 = tanhf(v1); }
            C[(size_t)r0    *DD + gc] = v0;
            C[(size_t)(r0+1)*DD + gc] = v1;
        }
    }
}

// ---------------- loss reduction ----------------------------------------------
__global__ void k_loss(const float* __restrict__ semb, const int* __restrict__ perm,
                       float* __restrict__ mi) {
    const int cj[6] = {1,2,3,2,3,3};
    int b = blockIdx.x, cnt = blockIdx.y;
    __shared__ float red[256];
    int tid = threadIdx.x;
    float c = 0.f;
    if (tid < DD) {
        float mu = g_o2[((size_t)(cnt*2+0)*BB + b)*DD + tid];
        float lv = g_o2[((size_t)(cnt*2+1)*BB + b)*DD + tid];
        int j = cj[cnt];
        float yj  = semb[(size_t)b*FD + j*DD + tid];
        float yjp = semb[(size_t)perm[b]*FD + j*DD + tid];
        float d1 = mu - yj, d2 = mu - yjp;
        c = (d2*d2 - d1*d1) * expf(-lv);
    }
    red[tid] = c; __syncthreads();
    for (int o = 128; o > 0; o >>= 1) {
        if (tid < o) red[tid] += red[tid+o];
        __syncthreads();
    }
    if (tid == 0) atomicAdd(mi, red[0] * (0.5f/BB));
}

// ---------------- launch --------------------------------------------------------
extern "C" void kernel_launch(void* const* d_in, const int* in_sizes, int n_in,
                              void* d_out, int out_size) {
    const int*   sub        = (const int*)  d_in[0];
    const int*   rel        = (const int*)  d_in[1];
    const int*   eidx       = (const int*)  d_in[2];
    const int*   etype      = (const int*)  d_in[3];
    const int*   perm       = (const int*)  d_in[4];
    const float* init_embed = (const float*)d_in[5];
    const float* init_rel   = (const float*)d_in[6];
    const float* pca_w      = (const float*)d_in[7];
    const float* pca_b      = (const float*)d_in[8];
    const float* cw_w       = (const float*)d_in[9];
    const float* w_rel      = (const float*)d_in[10];
    const float* mu_w1      = (const float*)d_in[11];
    const float* mu_b1      = (const float*)d_in[12];
    const float* mu_w2      = (const float*)d_in[13];
    const float* mu_b2      = (const float*)d_in[14];
    const float* lv_w1      = (const float*)d_in[15];
    const float* lv_b1      = (const float*)d_in[16];
    const float* lv_w2      = (const float*)d_in[17];
    const float* lv_b2      = (const float*)d_in[18];
    float* out = (float*)d_out;

    const int* src = eidx;
    const int* dst = eidx + EE;

    float *xA, *xB, *kw, *r1, *H;
    __half *xhA, *xhB;
    cudaGetSymbolAddress((void**)&xA, g_xA);
    cudaGetSymbolAddress((void**)&xB, g_xB);
    cudaGetSymbolAddress((void**)&kw, g_kw);
    cudaGetSymbolAddress((void**)&r1, g_r1);
    cudaGetSymbolAddress((void**)&H, g_h);
    cudaGetSymbolAddress((void**)&xhA, g_xhA);
    cudaGetSymbolAddress((void**)&xhB, g_xhB);

    const int NB = (NN + 255)/256;

    cudaStream_t s2;
    cudaStreamCreate(&s2);
    cudaEvent_t evFork, evJoin;
    cudaEventCreateWithFlags(&evFork, cudaEventDisableTiming);
    cudaEventCreateWithFlags(&evJoin, cudaEventDisableTiming);

    cudaEventRecord(evFork, 0);
    cudaStreamWaitEvent(s2, evFork, 0);

    // ---- stream s2: CSR build + r1 + rel_emb ----
    k_zero<<<NB, 256, 0, s2>>>(out + MI_OFF);
    k_hist<<<(EE + 255)/256, 256, 0, s2>>>(dst);
    k_scan1<<<NB, 256, 0, s2>>>();
    k_scan2<<<1, 256, 0, s2>>>(NB);
    k_scan3<<<NB, 256, 0, s2>>>();
    k_fill<<<(EE + 255)/256, 256, 0, s2>>>(src, dst, etype);
    {
        dim3 g((NRELD + 127)/128, (DD + 63)/64);
        k_sgemm4<<<g, 128, 0, s2>>>(init_rel, DD, w_rel, DD, nullptr, r1, DD,
                                    nullptr, NRELD, DD, DD, 0, 0);
    }
    k_relemb<<<BB, 256, 0, s2>>>(rel, init_rel, out + REL_OFF);
    cudaEventRecord(evJoin, s2);

    // ---- stream 0: big GEMMs ----
    {
        dim3 g((NN + 127)/128, (FD + 63)/64);
        k_sgemm4<<<g, 128>>>(init_embed, INITD, pca_w, FD, pca_b, xA, FD,
                             xhA, NN, FD, INITD, 1, 1);
    }
    {
        dim3 g((NN*FF + 127)/128, (DD + 63)/64);
        k_sgemm4<<<g, 128>>>(xA, DD, cw_w, DD, nullptr, xB, DD,
                             nullptr, NN*FF, DD, DD, 2, 0);
    }
    k_kwsm<<<(NN*DD + 255)/256, 256>>>(xB, kw);

    cudaStreamWaitEvent(0, evJoin, 0);

    // layers (fp16 gathers, 4-slot ring)
    k_layer4h<<<NN/4, 128>>>(xhA, kw, init_rel, nullptr, xhB, 0);
    k_layer4h<<<NN/4, 128>>>(xhB, kw, r1, out + X_OFF, nullptr, 1);

    // gathers + CLUB + loss
    k_subemb<<<BB, 256>>>(sub, out + X_OFF, out + SUB_OFF);
    {
        dim3 g(BB/64, (HH2 + 63)/64, 12);
        k_club1<<<g, 256>>>(out + SUB_OFF, mu_w1, mu_b1, lv_w1, lv_b1, H);
    }
    {
        dim3 g(BB/128, (DD + 63)/64, 12);
        k_club2g<<<g, 128>>>(mu_w2, mu_b2, lv_w2, lv_b2);
    }
    {
        dim3 g(BB, NPAIR);
        k_loss<<<g, 256>>>(out + SUB_OFF, perm, out + MI_OFF);
    }

    cudaEventDestroy(evFork);
    cudaEventDestroy(evJoin);
    cudaStreamDestroy(s2);
}

// round 17
// speedup vs baseline: 1.2229x; 1.2122x over previous
#include <cuda_runtime.h>
#include <cuda_pipeline.h>
#include <cuda_fp16.h>
#include <math.h>
#include <stdint.h>

#define NN    40000
#define INITD 100
#define DD    200
#define FF    4
#define EE    800000
#define NRELD 800
#define BB    2048
#define HH2   100
#define NPAIR 6
#define FD    (FF*DD)   // 800

#define SUB_OFF 0
#define REL_OFF ((size_t)BB*FD)
#define X_OFF   ((size_t)2*BB*FD)
#define MI_OFF  ((size_t)2*BB*FD + (size_t)NN*FD)

typedef unsigned long long u64t;

// ---------------- scratch ----------------------------------------------------
__device__ float g_xA[(size_t)NN*FD];   // head-major fp32 (x0)
__device__ float g_xB[(size_t)NN*FD];   // kw_raw temp
__device__ float g_kw[(size_t)NN*FD];
__device__ __align__(16) __half g_xhA[(size_t)NN*FD];  // fp16 x0
__device__ __align__(16) __half g_xhB[(size_t)NN*FD];  // fp16 layer0 out
__device__ __align__(16) __half g_cwh[DD*DD];          // fp16 cw_w
__device__ float g_r1[NRELD*DD];
__device__ float g_h[12*BB*HH2];
__device__ float g_o2[12*BB*DD];
__device__ int   g_deg[NN];
__device__ int   g_cur[NN];
__device__ int   g_rowptr[NN+1];
__device__ int   g_csrc[EE];
__device__ int   g_cet[EE];
__device__ int   g_bsums[256];
__device__ int   g_boffs[256];

// ---------------- helpers -----------------------------------------------------
__device__ __forceinline__ void ffma2(u64t& d, u64t a, u64t b) {
    asm("fma.rn.f32x2 %0, %1, %2, %0;" : "+l"(d) : "l"(a), "l"(b));
}
__device__ __forceinline__ u64t dup2(float x) {
    u64t r; asm("mov.b64 %0, {%1, %2};" : "=l"(r) : "f"(x), "f"(x)); return r;
}
__device__ __forceinline__ float2 unpack2(u64t v) {
    float lo, hi; asm("mov.b64 {%0, %1}, %2;" : "=f"(lo), "=f"(hi) : "l"(v));
    return make_float2(lo, hi);
}
__device__ __forceinline__ uint32_t smem_u32(const void* p) {
    return (uint32_t)__cvta_generic_to_shared(p);
}

// ---------------- CSR build ---------------------------------------------------
__global__ void k_zero(float* mi) {
    int i = blockIdx.x*blockDim.x + threadIdx.x;
    if (i < NN) { g_deg[i] = 0; g_cur[i] = 0; }
    if (i == 0) *mi = 0.f;
}
__global__ void k_hist(const int* __restrict__ dst) {
    int e = blockIdx.x*blockDim.x + threadIdx.x;
    if (e < EE) atomicAdd(&g_deg[dst[e]], 1);
}
__global__ void k_scan1() {
    __shared__ int s[256];
    int tid = threadIdx.x;
    int i = blockIdx.x*256 + tid;
    int v = (i < NN) ? g_deg[i] : 0;
    s[tid] = v; __syncthreads();
    for (int off = 1; off < 256; off <<= 1) {
        int t = (tid >= off) ? s[tid-off] : 0;
        __syncthreads(); s[tid] += t; __syncthreads();
    }
    if (i < NN) g_rowptr[i] = s[tid] - v;
    if (tid == 255) g_bsums[blockIdx.x] = s[255];
}
__global__ void k_scan2(int nb) {
    __shared__ int s[256];
    int tid = threadIdx.x;
    int v = (tid < nb) ? g_bsums[tid] : 0;
    s[tid] = v; __syncthreads();
    for (int off = 1; off < 256; off <<= 1) {
        int t = (tid >= off) ? s[tid-off] : 0;
        __syncthreads(); s[tid] += t; __syncthreads();
    }
    if (tid < nb) g_boffs[tid] = s[tid] - v;
}
__global__ void k_scan3() {
    int tid = threadIdx.x;
    int i = blockIdx.x*256 + tid;
    if (i < NN) g_rowptr[i] += g_boffs[blockIdx.x];
    if (i == 0) g_rowptr[NN] = EE;
}
__global__ void k_fill(const int* __restrict__ src, const int* __restrict__ dst,
                       const int* __restrict__ et) {
    int e = blockIdx.x*blockDim.x + threadIdx.x;
    if (e >= EE) return;
    int d = dst[e];
    int pos = g_rowptr[d] + atomicAdd(&g_cur[d], 1);
    g_csrc[pos] = src[e];
    g_cet[pos]  = et[e];
}

// ---------------- cw_w -> fp16 ------------------------------------------------
__global__ void k_cw2h(const float* __restrict__ cw) {
    int i = blockIdx.x*blockDim.x + threadIdx.x;
    if (i < DD*DD) g_cwh[i] = __float2half(cw[i]);
}

// ---------------- HMMA fp16 GEMM for kw: C = leaky(Ah @ Bh) -------------------
// Ah = g_xhA [M=160000][DD], Bh = g_cwh [DD][DD], C = g_xB row-major.
// Block 128 thr (4 warps), tile 128x64, warp-tile 32x64 (2 m16 x 8 n8), k16 steps.
__global__ __launch_bounds__(128, 4)
void k_hgemm(const __half* __restrict__ Ah, float* __restrict__ C) {
    __shared__ __align__(16) __half As[128][24];  // 16 k + pad to 48B rows
    __shared__ __align__(16) __half Bs[16][72];   // 64 n + pad to 144B rows
    int tid = threadIdx.x;
    int warp = tid >> 5, lane = tid & 31;
    int row0 = blockIdx.x * 128, col0 = blockIdx.y * 64;
    int wbase = warp * 32;

    float acc[2][8][4];
    #pragma unroll
    for (int mt = 0; mt < 2; mt++)
        #pragma unroll
        for (int nb = 0; nb < 8; nb++)
            #pragma unroll
            for (int c = 0; c < 4; c++) acc[mt][nb][c] = 0.f;

    for (int k0 = 0; k0 < DD; k0 += 16) {
        // A tile: 256 chunks of 8 halfs; thread handles chunks tid, tid+128
        #pragma unroll
        for (int it = 0; it < 2; it++) {
            int c = tid + it*128;
            int r = c >> 1, koff = (c & 1) * 8;
            uint4 v = make_uint4(0,0,0,0);
            if (k0 + koff < DD)
                v = *(const uint4*)(Ah + (size_t)(row0 + r)*DD + k0 + koff);
            *(uint4*)&As[r][koff] = v;
        }
        // B tile: 128 chunks of 8 halfs
        {
            int k = tid >> 3, nc = tid & 7;
            uint4 v = make_uint4(0,0,0,0);
            if (k0 + k < DD && col0 + nc*8 < DD)
                v = *(const uint4*)(g_cwh + (size_t)(k0 + k)*DD + col0 + nc*8);
            *(uint4*)&Bs[k][nc*8] = v;
        }
        __syncthreads();

        // B fragments (shared across both m16 tiles)
        uint32_t bf[8][2];
        {
            int krow = lane & 15;
            #pragma unroll
            for (int nb = 0; nb < 8; nb++) {
                uint32_t addr = smem_u32(&Bs[krow][nb*8]);
                asm volatile("ldmatrix.sync.aligned.m8n8.x2.trans.shared.b16 {%0,%1}, [%2];"
                    : "=r"(bf[nb][0]), "=r"(bf[nb][1]) : "r"(addr));
            }
        }
        // A fragments + MMAs
        #pragma unroll
        for (int mt = 0; mt < 2; mt++) {
            uint32_t af[4];
            int r = wbase + mt*16 + (lane & 15);
            int kk = (lane >> 4) * 8;
            uint32_t addr = smem_u32(&As[r][kk]);
            asm volatile("ldmatrix.sync.aligned.m8n8.x4.shared.b16 {%0,%1,%2,%3}, [%4];"
                : "=r"(af[0]), "=r"(af[1]), "=r"(af[2]), "=r"(af[3]) : "r"(addr));
            #pragma unroll
            for (int nb = 0; nb < 8; nb++) {
                asm volatile("mma.sync.aligned.m16n8k16.row.col.f32.f16.f16.f32 "
                    "{%0,%1,%2,%3}, {%4,%5,%6,%7}, {%8,%9}, {%0,%1,%2,%3};"
                    : "+f"(acc[mt][nb][0]), "+f"(acc[mt][nb][1]),
                      "+f"(acc[mt][nb][2]), "+f"(acc[mt][nb][3])
                    : "r"(af[0]), "r"(af[1]), "r"(af[2]), "r"(af[3]),
                      "r"(bf[nb][0]), "r"(bf[nb][1]));
            }
        }
        __syncthreads();
    }

    // epilogue: leaky(0.2), store fp32
    int g = lane >> 2, t = lane & 3;
    #pragma unroll
    for (int mt = 0; mt < 2; mt++) {
        #pragma unroll
        for (int nb = 0; nb < 8; nb++) {
            int col = col0 + nb*8 + t*2;
            if (col >= DD) continue;
            int r0 = row0 + wbase + mt*16 + g;
            #pragma unroll
            for (int c = 0; c < 4; c++) {
                int rr = r0 + (c >> 1)*8;
                int cc = col + (c & 1);
                if (cc >= DD) continue;
                float v = acc[mt][nb][c];
                v = (v > 0.f) ? v : 0.2f*v;
                C[(size_t)rr*DD + cc] = v;
            }
        }
    }
}

// ---------------- SGEMM v5: 128x64, coalesced A, f32x2 ----------------------
__global__ __launch_bounds__(128, 4)
void k_sgemm4(const float* __restrict__ A, int lda,
              const float* __restrict__ B, int ldb,
              const float* __restrict__ bias,
              float* __restrict__ C, int ldc,
              __half* __restrict__ Ch,
              int M, int N, int K, int act, int hm) {
    __shared__ __align__(16) float As[2][16][128];
    __shared__ __align__(16) float Bs[2][16][64];
    int tid = threadIdx.x;
    int tx = tid & 7, ty = tid >> 3;
    int row0 = blockIdx.x*128, col0 = blockIdx.y*64;
    int bk = tid >> 3, bc = (tid & 7) * 8;
    int arow = tid >> 2;
    int ak4  = (tid & 3) * 4;

    u64t acc[4][8];
    #pragma unroll
    for (int i = 0; i < 4; i++)
        #pragma unroll
        for (int j = 0; j < 8; j++) acc[i][j] = 0ull;

    float pa[16], pb[8];
    int nkt = (K + 15) >> 4;
    #pragma unroll 1
    for (int kt = -1; kt < nkt; kt++) {
        bool fastA = false;
        if (kt + 1 < nkt) {
            int k0 = (kt + 1) * 16;
            fastA = (k0 + 16 <= K) && (row0 + 128 <= M);
            if (fastA) {
                #pragma unroll
                for (int it = 0; it < 4; it++) {
                    float4 v = *(const float4*)(A + (size_t)(row0 + arow + it*32)*lda + k0 + ak4);
                    pa[it*4+0] = v.x; pa[it*4+1] = v.y; pa[it*4+2] = v.z; pa[it*4+3] = v.w;
                }
            } else {
                int gr = row0 + tid;
                #pragma unroll
                for (int c = 0; c < 16; c++)
                    pa[c] = (gr < M && k0 + c < K) ? A[(size_t)gr*lda + k0 + c] : 0.f;
            }
            if (k0 + bk < K && col0 + 64 <= N) {
                const float* bp = B + (size_t)(k0 + bk)*ldb + col0 + bc;
                float4 v0=*(const float4*)bp, v1=*(const float4*)(bp+4);
                pb[0]=v0.x;pb[1]=v0.y;pb[2]=v0.z;pb[3]=v0.w;
                pb[4]=v1.x;pb[5]=v1.y;pb[6]=v1.z;pb[7]=v1.w;
            } else {
                #pragma unroll
                for (int c = 0; c < 8; c++) {
                    int gc = col0 + bc + c;
                    pb[c] = (k0 + bk < K && gc < N) ? B[(size_t)(k0+bk)*ldb + gc] : 0.f;
                }
            }
        }
        if (kt >= 0) {
            int cur = kt & 1;
            #pragma unroll
            for (int kk = 0; kk < 16; kk++) {
                const ulonglong2* ap2 = (const ulonglong2*)&As[cur][kk][ty*8];
                ulonglong2 aA = ap2[0];
                ulonglong2 aB = ap2[1];
                float4 bv0 = *(const float4*)&Bs[cur][kk][tx*8];
                float4 bv1 = *(const float4*)&Bs[cur][kk][tx*8+4];
                u64t b[8];
                b[0]=dup2(bv0.x); b[1]=dup2(bv0.y); b[2]=dup2(bv0.z); b[3]=dup2(bv0.w);
                b[4]=dup2(bv1.x); b[5]=dup2(bv1.y); b[6]=dup2(bv1.z); b[7]=dup2(bv1.w);
                #pragma unroll
                for (int j = 0; j < 8; j++) {
                    ffma2(acc[0][j], aA.x, b[j]);
                    ffma2(acc[1][j], aA.y, b[j]);
                    ffma2(acc[2][j], aB.x, b[j]);
                    ffma2(acc[3][j], aB.y, b[j]);
                }
            }
        }
        if (kt + 1 < nkt) {
            int nxt = (kt + 1) & 1;
            if (fastA) {
                #pragma unroll
                for (int it = 0; it < 4; it++) {
                    int rr = arow + it*32;
                    As[nxt][ak4+0][rr] = pa[it*4+0];
                    As[nxt][ak4+1][rr] = pa[it*4+1];
                    As[nxt][ak4+2][rr] = pa[it*4+2];
                    As[nxt][ak4+3][rr] = pa[it*4+3];
                }
            } else {
                #pragma unroll
                for (int c = 0; c < 16; c++) As[nxt][c][tid] = pa[c];
            }
            *(float4*)&Bs[nxt][bk][bc]   = make_float4(pb[0],pb[1],pb[2],pb[3]);
            *(float4*)&Bs[nxt][bk][bc+4] = make_float4(pb[4],pb[5],pb[6],pb[7]);
        }
        __syncthreads();
    }

    #pragma unroll
    for (int i = 0; i < 4; i++) {
        int r0 = row0 + ty*8 + i*2;
        #pragma unroll
        for (int j = 0; j < 8; j++) {
            int gc = col0 + tx*8 + j;
            if (gc >= N) continue;
            float2 p = unpack2(acc[i][j]);
            float bv = bias ? bias[gc] : 0.f;
            float v0 = p.x + bv, v1 = p.y + bv;
            if (act == 1) { v0 = tanhf(v0); v1 = tanhf(v1); }
            else if (act == 2) { v0 = (v0 > 0.f) ? v0 : 0.2f*v0; v1 = (v1 > 0.f) ? v1 : 0.2f*v1; }
            if (hm) {
                int f = gc / DD, d = gc - f*DD;
                size_t base = (size_t)f*NN*DD + d;
                if (r0 < M) {
                    C[base + (size_t)r0*DD] = v0;
                    if (Ch) Ch[base + (size_t)r0*DD] = __float2half(v0);
                }
                if (r0 + 1 < M) {
                    C[base + (size_t)(r0+1)*DD] = v1;
                    if (Ch) Ch[base + (size_t)(r0+1)*DD] = __float2half(v1);
                }
            } else {
                if (r0     < M) C[(size_t)r0    *ldc + gc] = v0;
                if (r0 + 1 < M) C[(size_t)(r0+1)*ldc + gc] = v1;
            }
        }
    }
}

// ---------------- kw softmax over F axis (head-major) ------------------------
__global__ void k_kwsm(const float* __restrict__ raw, float* __restrict__ kw) {
    int i = blockIdx.x*blockDim.x + threadIdx.x;
    if (i >= NN*DD) return;
    const float* p = raw + i;
    const size_t S = (size_t)NN*DD;
    float a0 = __ldcs(p), a1 = __ldcs(p+S), a2 = __ldcs(p+2*S), a3 = __ldcs(p+3*S);
    float m = fmaxf(fmaxf(a0, a1), fmaxf(a2, a3));
    float e0 = __expf(a0-m), e1 = __expf(a1-m), e2 = __expf(a2-m), e3 = __expf(a3-m);
    float inv = 1.f/(e0+e1+e2+e3);
    float* q = kw + i;
    __stcs(q, e0*inv); __stcs(q+S, e1*inv); __stcs(q+2*S, e2*inv); __stcs(q+3*S, e3*inv);
}

// ---------------- attention layer: fp16 gathers, cp.async 4-slot ring --------
__global__ __launch_bounds__(128, 4)
void k_layer4h(const __half* __restrict__ xh, const float* __restrict__ kw,
               const float* __restrict__ r, float* __restrict__ xo_f,
               __half* __restrict__ xo_h, int mode) {
    __shared__ float  srd[4][4][DD];
    __shared__ __align__(16) __half sxh[4][4][4][DD];
    int warp = threadIdx.x >> 5, lane = threadIdx.x & 31;
    int v = blockIdx.x*4 + warp;
    bool on = lane < 25;
    int off = lane * 8;

    float xd[4][8], acc[4][8];
    float rm[4], rs[4];
    #pragma unroll
    for (int h = 0; h < 4; h++) {
        rm[h] = -INFINITY; rs[h] = 0.f;
        #pragma unroll
        for (int j = 0; j < 8; j++) { xd[h][j] = 0.f; acc[h][j] = 0.f; }
        if (on) {
            const __half2* p = (const __half2*)(xh + ((size_t)h*NN + v)*DD + off);
            #pragma unroll
            for (int q = 0; q < 4; q++) {
                float2 f = __half22float2(p[q]);
                xd[h][q*2] = f.x; xd[h][q*2+1] = f.y;
            }
        }
    }

    int e0 = g_rowptr[v], e1 = g_rowptr[v+1];

    auto issue = [&](int e) {
        int slot = e & 3;
        if (on) {
            int s  = g_csrc[e];
            int et = g_cet[e];
            const float* rg = r + (size_t)et*DD + off;
            float* rd = &srd[warp][slot][off];
            __pipeline_memcpy_async(rd,     rg,     16);
            __pipeline_memcpy_async(rd + 4, rg + 4, 16);
            #pragma unroll
            for (int h = 0; h < 4; h++) {
                const __half* xg = xh + ((size_t)h*NN + s)*DD + off;
                __half* xdst = &sxh[warp][slot][h][off];
                __pipeline_memcpy_async(xdst, xg, 16);
            }
        }
        __pipeline_commit();
    };

    if (e0     < e1) issue(e0);     else __pipeline_commit();
    if (e0 + 1 < e1) issue(e0 + 1); else __pipeline_commit();
    if (e0 + 2 < e1) issue(e0 + 2); else __pipeline_commit();

    for (int e = e0; e < e1; ++e) {
        if (e + 3 < e1) issue(e + 3); else __pipeline_commit();
        __pipeline_wait_prior(3);
        int slot = e & 3;

        float xsr[4][8];
        float p[4] = {0.f, 0.f, 0.f, 0.f};
        if (on) {
            float rr[8];
            {
                const float4* rp = (const float4*)&srd[warp][slot][off];
                float4 a = rp[0], b = rp[1];
                rr[0]=a.x; rr[1]=a.y; rr[2]=a.z; rr[3]=a.w;
                rr[4]=b.x; rr[5]=b.y; rr[6]=b.z; rr[7]=b.w;
            }
            #pragma unroll
            for (int h = 0; h < 4; h++) {
                const __half2* xp = (const __half2*)&sxh[warp][slot][h][off];
                float sum = 0.f;
                #pragma unroll
                for (int q = 0; q < 4; q++) {
                    float2 f = __half22float2(xp[q]);
                    xsr[h][q*2]   = f.x * rr[q*2];
                    xsr[h][q*2+1] = f.y * rr[q*2+1];
                    sum += xsr[h][q*2]*xd[h][q*2] + xsr[h][q*2+1]*xd[h][q*2+1];
                }
                p[h] = sum;
            }
        } else {
            #pragma unroll
            for (int h = 0; h < 4; h++)
                #pragma unroll
                for (int j = 0; j < 8; j++) xsr[h][j] = 0.f;
        }
        #pragma unroll
        for (int o = 16; o > 0; o >>= 1) {
            p[0] += __shfl_xor_sync(0xffffffffu, p[0], o);
            p[1] += __shfl_xor_sync(0xffffffffu, p[1], o);
            p[2] += __shfl_xor_sync(0xffffffffu, p[2], o);
            p[3] += __shfl_xor_sync(0xffffffffu, p[3], o);
        }
        #pragma unroll
        for (int h = 0; h < 4; h++) {
            float dot = p[h];
            float l = (dot > 0.f) ? dot : 0.2f*dot;
            float nm = fmaxf(rm[h], l);
            float sc = (rm[h] == -INFINITY) ? 0.f : __expf(rm[h] - nm);
            float w = __expf(l - nm);
            rm[h] = nm; rs[h] = rs[h]*sc + w;
            #pragma unroll
            for (int j = 0; j < 8; j++)
                acc[h][j] = acc[h][j]*sc + w*xsr[h][j];
        }
    }
    if (!on) return;
    #pragma unroll
    for (int h = 0; h < 4; h++) {
        float inv = 1.f/(rs[h] + 1e-16f);
        const float4* kwp = (const float4*)(kw + ((size_t)h*NN + v)*DD + off);
        float4 ka = __ldcs(kwp), kb = __ldcs(kwp+1);
        float kk[8] = {ka.x, ka.y, ka.z, ka.w, kb.x, kb.y, kb.z, kb.w};
        float o[8];
        #pragma unroll
        for (int j = 0; j < 8; j++) o[j] = tanhf(acc[h][j]*inv) * kk[j];
        if (mode == 0) {
            __half2 h2[4];
            #pragma unroll
            for (int q = 0; q < 4; q++) h2[q] = __floats2half2_rn(o[q*2], o[q*2+1]);
            *(uint4*)(xo_h + ((size_t)h*NN + v)*DD + off) = *(uint4*)h2;
        } else {
            float* w = xo_f + (size_t)v*FD + (size_t)h*DD + off;
            __stcs((float4*)w,     make_float4(o[0], o[1], o[2], o[3]));
            __stcs((float4*)w + 1, make_float4(o[4], o[5], o[6], o[7]));
        }
    }
}

// ---------------- output gathers ----------------------------------------------
__global__ void k_subemb(const int* __restrict__ sub, const float* __restrict__ x,
                         float* __restrict__ o) {
    int b = blockIdx.x;
    int row = sub[b];
    for (int idx = threadIdx.x; idx < FD; idx += blockDim.x)
        o[(size_t)b*FD + idx] = x[(size_t)row*FD + idx];
}
__global__ void k_relemb(const int* __restrict__ rel, const float* __restrict__ ir,
                         float* __restrict__ o) {
    int b = blockIdx.x;
    int row = rel[b];
    for (int idx = threadIdx.x; idx < FD; idx += blockDim.x) {
        int d = idx % DD;
        o[(size_t)b*FD + idx] = ir[(size_t)row*DD + d];
    }
}

// ---------------- CLUB layer 1 (12 batched GEMMs, relu) ----------------------
__global__ void k_club1(const float* __restrict__ semb,
                        const float* __restrict__ mu_w1, const float* __restrict__ mu_b1,
                        const float* __restrict__ lv_w1, const float* __restrict__ lv_b1,
                        float* __restrict__ H) {
    const int ci[6] = {0,0,0,1,1,2};
    int z = blockIdx.z, cnt = z >> 1, net = z & 1;
    const float* A  = semb + ci[cnt]*DD;
    const float* W  = (net ? lv_w1 : mu_w1) + (size_t)cnt*DD*HH2;
    const float* bb = (net ? lv_b1 : mu_b1) + cnt*HH2;
    float* C = H + (size_t)z*BB*HH2;

    __shared__ float As[8][64];
    __shared__ float Bs[8][65];
    int tid = threadIdx.x;
    int tx = tid & 15, ty = tid >> 4;
    int row0 = blockIdx.x*64, col0 = blockIdx.y*64;
    float acc[4][4] = {};
    for (int k0 = 0; k0 < DD; k0 += 8) {
        #pragma unroll
        for (int i = 0; i < 2; i++) {
            int idx = tid*2 + i;
            int rI = idx >> 3, kk = idx & 7;
            As[kk][rI] = A[(size_t)(row0+rI)*FD + k0 + kk];
        }
        #pragma unroll
        for (int i = 0; i < 2; i++) {
            int idx = tid + i*256;
            int kk = idx >> 6, c = idx & 63;
            int gc = col0 + c;
            Bs[kk][c] = (gc < HH2) ? W[(size_t)(k0+kk)*HH2 + gc] : 0.f;
        }
        __syncthreads();
        #pragma unroll
        for (int kk = 0; kk < 8; kk++) {
            float a[4], b[4];
            #pragma unroll
            for (int i = 0; i < 4; i++) a[i] = As[kk][ty*4+i];
            #pragma unroll
            for (int j = 0; j < 4; j++) b[j] = Bs[kk][tx*4+j];
            #pragma unroll
            for (int i = 0; i < 4; i++)
                #pragma unroll
                for (int j = 0; j < 4; j++)
                    acc[i][j] += a[i]*b[j];
        }
        __syncthreads();
    }
    #pragma unroll
    for (int i = 0; i < 4; i++) {
        int gr = row0 + ty*4 + i;
        #pragma unroll
        for (int j = 0; j < 4; j++) {
            int gc = col0 + tx*4 + j;
            if (gc < HH2)
                C[(size_t)gr*HH2 + gc] = fmaxf(acc[i][j] + bb[gc], 0.f);
        }
    }
}

// ---------------- CLUB layer 2 as batched GEMM (z = pair*2 + net) -----------
__global__ __launch_bounds__(128, 4)
void k_club2g(const float* __restrict__ mu_w2, const float* __restrict__ mu_b2,
              const float* __restrict__ lv_w2, const float* __restrict__ lv_b2) {
    __shared__ __align__(16) float As[2][16][128];
    __shared__ __align__(16) float Bs[2][16][64];
    int z = blockIdx.z, cnt = z >> 1, net = z & 1;
    const float* A  = g_h + (size_t)z*BB*HH2;
    const float* W  = (net ? lv_w2 : mu_w2) + (size_t)cnt*HH2*DD;
    const float* bb = (net ? lv_b2 : mu_b2) + cnt*DD;
    float* C = g_o2 + (size_t)z*BB*DD;
    const int N = DD, K = HH2;
    int tid = threadIdx.x;
    int tx = tid & 7, ty = tid >> 3;
    int row0 = blockIdx.x*128, col0 = blockIdx.y*64;
    int bk = tid >> 3, bc = (tid & 7) * 8;

    u64t acc[4][8];
    #pragma unroll
    for (int i = 0; i < 4; i++)
        #pragma unroll
        for (int j = 0; j < 8; j++) acc[i][j] = 0ull;

    float pa[16], pb[8];
    int nkt = (K + 15) >> 4;
    #pragma unroll 1
    for (int kt = -1; kt < nkt; kt++) {
        if (kt + 1 < nkt) {
            int k0 = (kt + 1) * 16;
            int gr = row0 + tid;
            #pragma unroll
            for (int c = 0; c < 16; c++)
                pa[c] = (k0 + c < K) ? A[(size_t)gr*HH2 + k0 + c] : 0.f;
            #pragma unroll
            for (int c = 0; c < 8; c++) {
                int gc = col0 + bc + c;
                pb[c] = (k0 + bk < K && gc < N) ? W[(size_t)(k0+bk)*DD + gc] : 0.f;
            }
        }
        if (kt >= 0) {
            int cur = kt & 1;
            #pragma unroll
            for (int kk = 0; kk < 16; kk++) {
                const ulonglong2* ap2 = (const ulonglong2*)&As[cur][kk][ty*8];
                ulonglong2 aA = ap2[0];
                ulonglong2 aB = ap2[1];
                float4 bv0 = *(const float4*)&Bs[cur][kk][tx*8];
                float4 bv1 = *(const float4*)&Bs[cur][kk][tx*8+4];
                u64t b[8];
                b[0]=dup2(bv0.x); b[1]=dup2(bv0.y); b[2]=dup2(bv0.z); b[3]=dup2(bv0.w);
                b[4]=dup2(bv1.x); b[5]=dup2(bv1.y); b[6]=dup2(bv1.z); b[7]=dup2(bv1.w);
                #pragma unroll
                for (int j = 0; j < 8; j++) {
                    ffma2(acc[0][j], aA.x, b[j]);
                    ffma2(acc[1][j], aA.y, b[j]);
                    ffma2(acc[2][j], aB.x, b[j]);
                    ffma2(acc[3][j], aB.y, b[j]);
                }
            }
        }
        if (kt + 1 < nkt) {
            int nxt = (kt + 1) & 1;
            #pragma unroll
            for (int c = 0; c < 16; c++) As[nxt][c][tid] = pa[c];
            *(float4*)&Bs[nxt][bk][bc]   = make_float4(pb[0],pb[1],pb[2],pb[3]);
            *(float4*)&Bs[nxt][bk][bc+4] = make_float4(pb[4],pb[5],pb[6],pb[7]);
        }
        __syncthreads();
    }
    #pragma unroll
    for (int i = 0; i < 4; i++) {
        int r0 = row0 + ty*8 + i*2;
        #pragma unroll
        for (int j = 0; j < 8; j++) {
            int gc = col0 + tx*8 + j;
            if (gc >= N) continue;
            float2 p = unpack2(acc[i][j]);
            float bv = bb[gc];
            float v0 = p.x + bv, v1 = p.y + bv;
            if (net) { v0 = tanhf(v0); v1 = tanhf(v1); }
            C[(size_t)r0    *DD + gc] = v0;
            C[(size_t)(r0+1)*DD + gc] = v1;
        }
    }
}

// ---------------- loss reduction ----------------------------------------------
__global__ void k_loss(const float* __restrict__ semb, const int* __restrict__ perm,
                       float* __restrict__ mi) {
    const int cj[6] = {1,2,3,2,3,3};
    int b = blockIdx.x, cnt = blockIdx.y;
    __shared__ float red[256];
    int tid = threadIdx.x;
    float c = 0.f;
    if (tid < DD) {
        float mu = g_o2[((size_t)(cnt*2+0)*BB + b)*DD + tid];
        float lv = g_o2[((size_t)(cnt*2+1)*BB + b)*DD + tid];
        int j = cj[cnt];
        float yj  = semb[(size_t)b*FD + j*DD + tid];
        float yjp = semb[(size_t)perm[b]*FD + j*DD + tid];
        float d1 = mu - yj, d2 = mu - yjp;
        c = (d2*d2 - d1*d1) * expf(-lv);
    }
    red[tid] = c; __syncthreads();
    for (int o = 128; o > 0; o >>= 1) {
        if (tid < o) red[tid] += red[tid+o];
        __syncthreads();
    }
    if (tid == 0) atomicAdd(mi, red[0] * (0.5f/BB));
}

// ---------------- launch --------------------------------------------------------
extern "C" void kernel_launch(void* const* d_in, const int* in_sizes, int n_in,
                              void* d_out, int out_size) {
    const int*   sub        = (const int*)  d_in[0];
    const int*   rel        = (const int*)  d_in[1];
    const int*   eidx       = (const int*)  d_in[2];
    const int*   etype      = (const int*)  d_in[3];
    const int*   perm       = (const int*)  d_in[4];
    const float* init_embed = (const float*)d_in[5];
    const float* init_rel   = (const float*)d_in[6];
    const float* pca_w      = (const float*)d_in[7];
    const float* pca_b      = (const float*)d_in[8];
    const float* cw_w       = (const float*)d_in[9];
    const float* w_rel      = (const float*)d_in[10];
    const float* mu_w1      = (const float*)d_in[11];
    const float* mu_b1      = (const float*)d_in[12];
    const float* mu_w2      = (const float*)d_in[13];
    const float* mu_b2      = (const float*)d_in[14];
    const float* lv_w1      = (const float*)d_in[15];
    const float* lv_b1      = (const float*)d_in[16];
    const float* lv_w2      = (const float*)d_in[17];
    const float* lv_b2      = (const float*)d_in[18];
    float* out = (float*)d_out;

    const int* src = eidx;
    const int* dst = eidx + EE;

    float *xA, *xB, *kw, *r1, *H;
    __half *xhA, *xhB;
    cudaGetSymbolAddress((void**)&xA, g_xA);
    cudaGetSymbolAddress((void**)&xB, g_xB);
    cudaGetSymbolAddress((void**)&kw, g_kw);
    cudaGetSymbolAddress((void**)&r1, g_r1);
    cudaGetSymbolAddress((void**)&H, g_h);
    cudaGetSymbolAddress((void**)&xhA, g_xhA);
    cudaGetSymbolAddress((void**)&xhB, g_xhB);

    const int NB = (NN + 255)/256;

    cudaStream_t s2;
    cudaStreamCreate(&s2);
    cudaEvent_t evFork, evJoin;
    cudaEventCreateWithFlags(&evFork, cudaEventDisableTiming);
    cudaEventCreateWithFlags(&evJoin, cudaEventDisableTiming);

    cudaEventRecord(evFork, 0);
    cudaStreamWaitEvent(s2, evFork, 0);

    // ---- stream s2: CSR build + r1 + rel_emb ----
    k_zero<<<NB, 256, 0, s2>>>(out + MI_OFF);
    k_hist<<<(EE + 255)/256, 256, 0, s2>>>(dst);
    k_scan1<<<NB, 256, 0, s2>>>();
    k_scan2<<<1, 256, 0, s2>>>(NB);
    k_scan3<<<NB, 256, 0, s2>>>();
    k_fill<<<(EE + 255)/256, 256, 0, s2>>>(src, dst, etype);
    {
        dim3 g((NRELD + 127)/128, (DD + 63)/64);
        k_sgemm4<<<g, 128, 0, s2>>>(init_rel, DD, w_rel, DD, nullptr, r1, DD,
                                    nullptr, NRELD, DD, DD, 0, 0);
    }
    k_relemb<<<BB, 256, 0, s2>>>(rel, init_rel, out + REL_OFF);
    cudaEventRecord(evJoin, s2);

    // ---- stream 0: cw->fp16, x0 GEMM (fp32), kw GEMM (HMMA fp16), softmax ----
    k_cw2h<<<(DD*DD + 255)/256, 256>>>(cw_w);
    {
        dim3 g((NN + 127)/128, (FD + 63)/64);
        k_sgemm4<<<g, 128>>>(init_embed, INITD, pca_w, FD, pca_b, xA, FD,
                             xhA, NN, FD, INITD, 1, 1);
    }
    {
        dim3 g((NN*FF)/128, 4);   // 1250 x 4
        k_hgemm<<<g, 128>>>(xhA, xB);
    }
    k_kwsm<<<(NN*DD + 255)/256, 256>>>(xB, kw);

    cudaStreamWaitEvent(0, evJoin, 0);

    // layers (fp16 gathers, 4-slot ring)
    k_layer4h<<<NN/4, 128>>>(xhA, kw, init_rel, nullptr, xhB, 0);
    k_layer4h<<<NN/4, 128>>>(xhB, kw, r1, out + X_OFF, nullptr, 1);

    // gathers + CLUB + loss
    k_subemb<<<BB, 256>>>(sub, out + X_OFF, out + SUB_OFF);
    {
        dim3 g(BB/64, (HH2 + 63)/64, 12);
        k_club1<<<g, 256>>>(out + SUB_OFF, mu_w1, mu_b1, lv_w1, lv_b1, H);
    }
    {
        dim3 g(BB/128, (DD + 63)/64, 12);
        k_club2g<<<g, 128>>>(mu_w2, mu_b2, lv_w2, lv_b2);
    }
    {
        dim3 g(BB, NPAIR);
        k_loss<<<g, 256>>>(out + SUB_OFF, perm, out + MI_OFF);
    }

    cudaEventDestroy(evFork);
    cudaEventDestroy(evJoin);
    cudaStreamDestroy(s2);
}